// round 14
// baseline (speedup 1.0000x reference)
#include <cuda_runtime.h>
#include <cuda_bf16.h>
#include <cstdint>
#include <math.h>

#define NN    50000
#define EE    400000
#define ETOT  (NN + EE)
#define CH    256           // channels (HEADS*HID and OUT)
#define KIN   20
#define NEG_SLOPE 0.2f
#define EPSS  1e-16f

// ---------------- scratch (static device globals; no allocations) ----------
__device__ float g_xl1[NN * CH];
__device__ float g_xr1[NN * CH];
__device__ float g_h[NN * CH];      // ELU(layer-1 output)
__device__ float g_xl2[NN * CH];
__device__ float g_xr2[NN * CH];
__device__ int   g_deg[NN];         // degree counts, then scatter cursor
__device__ int   g_off[NN + 1];     // CSR offsets
__device__ int   g_part[64];        // scan block partials
__device__ int   g_csr_src[ETOT];
// bf16 hi/lo staging for tensor-core GEMM
__device__ __nv_bfloat16 g_h_hi[NN * CH];
__device__ __nv_bfloat16 g_h_lo[NN * CH];
__device__ __nv_bfloat16 g_wl_hi[CH * CH];   // transposed: [n][k]
__device__ __nv_bfloat16 g_wl_lo[CH * CH];
__device__ __nv_bfloat16 g_wr_hi[CH * CH];
__device__ __nv_bfloat16 g_wr_lo[CH * CH];

__device__ __forceinline__ float lrelu(float v) {
    return v > 0.0f ? v : NEG_SLOPE * v;
}

// m16n8k16 bf16 MMA, fp32 accumulate (sm_80+ baseline PTX; legacy HMMA pipe)
__device__ __forceinline__ void mma_bf16(float4& d,
                                         uint32_t a0, uint32_t a1,
                                         uint32_t a2, uint32_t a3,
                                         uint32_t b0, uint32_t b1) {
    asm volatile(
        "mma.sync.aligned.m16n8k16.row.col.f32.bf16.bf16.f32 "
        "{%0,%1,%2,%3}, {%4,%5,%6,%7}, {%8,%9}, {%0,%1,%2,%3};"
        : "+f"(d.x), "+f"(d.y), "+f"(d.z), "+f"(d.w)
        : "r"(a0), "r"(a1), "r"(a2), "r"(a3), "r"(b0), "r"(b1));
}

// ================= CSR construction =================
__global__ void zero_deg() {
    int i = blockIdx.x * blockDim.x + threadIdx.x;
    if (i < NN) g_deg[i] = 0;
}

__global__ void csr_count(const int* __restrict__ ei) {
    int e = blockIdx.x * blockDim.x + threadIdx.x;
    if (e >= ETOT) return;
    int dst = (e < EE) ? ei[EE + e] : e - EE;
    atomicAdd(&g_deg[dst], 1);
}

__global__ void scan1() {
    int tid = threadIdx.x;
    int lane = tid & 31, wid = tid >> 5;
    __shared__ int wsum[32];
    int i = blockIdx.x * 1024 + tid;
    int v = (i < NN) ? g_deg[i] : 0;
    if (i < NN) g_deg[i] = 0;
    int x = v;
    #pragma unroll
    for (int o = 1; o < 32; o <<= 1) {
        int y = __shfl_up_sync(0xffffffffu, x, o);
        if (lane >= o) x += y;
    }
    if (lane == 31) wsum[wid] = x;
    __syncthreads();
    if (wid == 0) {
        int w = wsum[lane];
        #pragma unroll
        for (int o = 1; o < 32; o <<= 1) {
            int y = __shfl_up_sync(0xffffffffu, w, o);
            if (lane >= o) w += y;
        }
        wsum[lane] = w;
    }
    __syncthreads();
    int incl = x + (wid > 0 ? wsum[wid - 1] : 0);
    if (i < NN) g_off[i] = incl - v;
    if (tid == 1023) g_part[blockIdx.x] = incl;
}

__global__ void scan2(int nblk) {
    __shared__ int sp[64];
    int t = threadIdx.x;
    sp[t] = (t < nblk) ? g_part[t] : 0;
    __syncthreads();
    if (t == 0) {
        int run = 0;
        for (int i = 0; i < nblk; i++) { int tmp = sp[i]; sp[i] = run; run += tmp; }
    }
    __syncthreads();
    if (t < nblk) g_part[t] = sp[t];
}

__global__ void scan3() {
    int i = blockIdx.x * 1024 + threadIdx.x;
    if (i < NN) g_off[i] += g_part[blockIdx.x];
    if (i == 0) g_off[NN] = ETOT;
}

__global__ void csr_scatter(const int* __restrict__ ei) {
    int e = blockIdx.x * blockDim.x + threadIdx.x;
    if (e >= ETOT) return;
    int src, dst;
    if (e < EE) { src = ei[e]; dst = ei[EE + e]; }
    else        { src = dst = e - EE; }
    int pos = g_off[dst] + atomicAdd(&g_deg[dst], 1);
    g_csr_src[pos] = src;
}

// ================= layer-1 GEMM: x[N,20]@W[20,256]+b, 64 rows/block ========
__global__ void gemm1_kernel(const float* __restrict__ x,
                             const float* __restrict__ Wl, const float* __restrict__ bl,
                             const float* __restrict__ Wr, const float* __restrict__ br) {
    __shared__ float swl[KIN * 256];
    __shared__ float swr[KIN * 256];
    __shared__ float sx[64][KIN];
    int tid = threadIdx.x;
    for (int i = tid; i < KIN * 256; i += 256) { swl[i] = Wl[i]; swr[i] = Wr[i]; }
    int nb = blockIdx.x * 64;
    for (int i = tid; i < 64 * KIN; i += 256) {
        int node = nb + i / KIN;
        sx[i / KIN][i % KIN] = (node < NN) ? x[node * KIN + (i % KIN)] : 0.0f;
    }
    __syncthreads();
    float bL = bl[tid], bR = br[tid];
    #pragma unroll 4
    for (int i = 0; i < 64; i++) {
        int node = nb + i;
        if (node >= NN) break;
        float al = bL, ar = bR;
        #pragma unroll
        for (int k = 0; k < KIN; k++) {
            float xv = sx[i][k];
            al = fmaf(xv, swl[k * 256 + tid], al);
            ar = fmaf(xv, swr[k * 256 + tid], ar);
        }
        g_xl1[node * 256 + tid] = al;
        g_xr1[node * 256 + tid] = ar;
    }
}

// ================= bf16 hi/lo conversions ====================================
__global__ void conv_h() {
    int i = blockIdx.x * blockDim.x + threadIdx.x;
    if (i >= NN * CH) return;
    float f = g_h[i];
    __nv_bfloat16 h = __float2bfloat16(f);
    g_h_hi[i] = h;
    g_h_lo[i] = __float2bfloat16(f - __bfloat162float(h));
}

__global__ void conv_w(const float* __restrict__ Wl, const float* __restrict__ Wr) {
    int idx = blockIdx.x * blockDim.x + threadIdx.x;
    if (idx >= CH * CH) return;
    int k = idx >> 8, n = idx & 255;
    float vl = Wl[k * 256 + n];
    float vr = Wr[k * 256 + n];
    __nv_bfloat16 hl = __float2bfloat16(vl);
    __nv_bfloat16 hr = __float2bfloat16(vr);
    g_wl_hi[n * 256 + k] = hl;
    g_wl_lo[n * 256 + k] = __float2bfloat16(vl - __bfloat162float(hl));
    g_wr_hi[n * 256 + k] = hr;
    g_wr_lo[n * 256 + k] = __float2bfloat16(vr - __bfloat162float(hr));
}

// ================= layer-2 GEMM on HMMA (3-term bf16 split) =================
// grid (391, 4), 256 threads = 8 warps. Warp computes 16 rows x 64 cols for
// BOTH W_l2 and W_r2. Fragments loaded directly from k-contiguous bf16 arrays.
__global__ void __launch_bounds__(256)
gemm_mma(const float* __restrict__ bl, const float* __restrict__ br) {
    int tid = threadIdx.x;
    int warp = tid >> 5, lane = tid & 31;
    int gID = lane >> 2, tig = lane & 3;
    int r0 = blockIdx.x * 128 + warp * 16;
    int col0 = blockIdx.y * 64;
    int rowA = r0 + gID;
    bool v0 = rowA < NN, v1 = (rowA + 8) < NN;

    const uint32_t* Ah = (const uint32_t*)g_h_hi;   // [row*128 + kword]
    const uint32_t* Al = (const uint32_t*)g_h_lo;
    const uint32_t* BLh = (const uint32_t*)g_wl_hi; // [n*128 + kword]
    const uint32_t* BLl = (const uint32_t*)g_wl_lo;
    const uint32_t* BRh = (const uint32_t*)g_wr_hi;
    const uint32_t* BRl = (const uint32_t*)g_wr_lo;

    float4 accL[8], accR[8];
    #pragma unroll
    for (int nt = 0; nt < 8; nt++) {
        accL[nt] = make_float4(0.f, 0.f, 0.f, 0.f);
        accR[nt] = make_float4(0.f, 0.f, 0.f, 0.f);
    }

    long base0 = (long)rowA * 128;
    long base1 = (long)(rowA + 8) * 128;

    for (int kt = 0; kt < 16; kt++) {
        int kw = kt * 8 + tig;             // word index of k pair
        uint32_t a0 = v0 ? Ah[base0 + kw]     : 0u;
        uint32_t a1 = v1 ? Ah[base1 + kw]     : 0u;
        uint32_t a2 = v0 ? Ah[base0 + kw + 4] : 0u;
        uint32_t a3 = v1 ? Ah[base1 + kw + 4] : 0u;
        uint32_t l0 = v0 ? Al[base0 + kw]     : 0u;
        uint32_t l1 = v1 ? Al[base1 + kw]     : 0u;
        uint32_t l2 = v0 ? Al[base0 + kw + 4] : 0u;
        uint32_t l3 = v1 ? Al[base1 + kw + 4] : 0u;
        #pragma unroll
        for (int nt = 0; nt < 8; nt++) {
            int bb = (col0 + nt * 8 + gID) * 128 + kw;
            uint32_t bh0 = BLh[bb], bh1 = BLh[bb + 4];
            uint32_t bw0 = BLl[bb], bw1 = BLl[bb + 4];
            mma_bf16(accL[nt], a0, a1, a2, a3, bh0, bh1);
            mma_bf16(accL[nt], l0, l1, l2, l3, bh0, bh1);
            mma_bf16(accL[nt], a0, a1, a2, a3, bw0, bw1);
            uint32_t ch0 = BRh[bb], ch1 = BRh[bb + 4];
            uint32_t cw0 = BRl[bb], cw1 = BRl[bb + 4];
            mma_bf16(accR[nt], a0, a1, a2, a3, ch0, ch1);
            mma_bf16(accR[nt], l0, l1, l2, l3, ch0, ch1);
            mma_bf16(accR[nt], a0, a1, a2, a3, cw0, cw1);
        }
    }

    // epilogue: c0,c1 = row gID cols tig*2,+1; c2,c3 = row gID+8 same cols
    #pragma unroll
    for (int nt = 0; nt < 8; nt++) {
        int cc = col0 + nt * 8 + tig * 2;
        float2 bLv = *(const float2*)&bl[cc];
        float2 bRv = *(const float2*)&br[cc];
        if (v0) {
            *(float2*)&g_xl2[rowA * 256 + cc] =
                make_float2(accL[nt].x + bLv.x, accL[nt].y + bLv.y);
            *(float2*)&g_xr2[rowA * 256 + cc] =
                make_float2(accR[nt].x + bRv.x, accR[nt].y + bRv.y);
        }
        if (v1) {
            *(float2*)&g_xl2[(rowA + 8) * 256 + cc] =
                make_float2(accL[nt].z + bLv.x, accL[nt].w + bLv.y);
            *(float2*)&g_xr2[(rowA + 8) * 256 + cc] =
                make_float2(accR[nt].z + bRv.x, accR[nt].w + bRv.y);
        }
    }
}

// ================= fused edge pass (R7): 2-edge pipelined online softmax ====
template<int LAYER>
__global__ void fused_edge(const float* __restrict__ att,
                           const float* __restrict__ bias,
                           float* __restrict__ out_arg) {
    const float* __restrict__ xl = (LAYER == 1) ? g_xl1 : g_xl2;
    const float* __restrict__ xr = (LAYER == 1) ? g_xr1 : g_xr2;

    int node = (blockIdx.x * blockDim.x + threadIdx.x) >> 5;
    int lane = threadIdx.x & 31;
    if (node >= NN) return;
    int s0 = g_off[node], s1 = g_off[node + 1];
    int c = lane * 8;

    const float4* pr = (const float4*)(xr + node * CH + c);
    float4 r0 = pr[0], r1 = pr[1];
    const float4* pa = (const float4*)(att + c);
    float4 w0 = pa[0], w1 = pa[1];

    float m = -INFINITY, ssum = 0.0f;
    float4 acc0 = make_float4(0.f, 0.f, 0.f, 0.f);
    float4 acc1 = make_float4(0.f, 0.f, 0.f, 0.f);

    float4 A0, A1, B0, B1;
    {
        const float4* p = (const float4*)(xl + g_csr_src[s0] * CH + c);
        A0 = p[0]; A1 = p[1];
    }
    if (s0 + 1 < s1) {
        const float4* p = (const float4*)(xl + g_csr_src[s0 + 1] * CH + c);
        B0 = p[0]; B1 = p[1];
    }

    int s = s0;
    for (; s + 1 < s1; s += 2) {
        float4 c0 = A0, c1 = A1, d0 = B0, d1 = B1;
        if (s + 2 < s1) {
            const float4* p = (const float4*)(xl + g_csr_src[s + 2] * CH + c);
            A0 = p[0]; A1 = p[1];
        }
        if (s + 3 < s1) {
            const float4* p = (const float4*)(xl + g_csr_src[s + 3] * CH + c);
            B0 = p[0]; B1 = p[1];
        }
        float p1, p2;
        p1  =        w0.x * lrelu(c0.x + r0.x);
        p2  =        w0.x * lrelu(d0.x + r0.x);
        p1 = fmaf(w0.y, lrelu(c0.y + r0.y), p1);
        p2 = fmaf(w0.y, lrelu(d0.y + r0.y), p2);
        p1 = fmaf(w0.z, lrelu(c0.z + r0.z), p1);
        p2 = fmaf(w0.z, lrelu(d0.z + r0.z), p2);
        p1 = fmaf(w0.w, lrelu(c0.w + r0.w), p1);
        p2 = fmaf(w0.w, lrelu(d0.w + r0.w), p2);
        p1 = fmaf(w1.x, lrelu(c1.x + r1.x), p1);
        p2 = fmaf(w1.x, lrelu(d1.x + r1.x), p2);
        p1 = fmaf(w1.y, lrelu(c1.y + r1.y), p1);
        p2 = fmaf(w1.y, lrelu(d1.y + r1.y), p2);
        p1 = fmaf(w1.z, lrelu(c1.z + r1.z), p1);
        p2 = fmaf(w1.z, lrelu(d1.z + r1.z), p2);
        p1 = fmaf(w1.w, lrelu(c1.w + r1.w), p1);
        p2 = fmaf(w1.w, lrelu(d1.w + r1.w), p2);
        if (LAYER == 1) {
            p1 += __shfl_xor_sync(0xffffffffu, p1, 4);
            p2 += __shfl_xor_sync(0xffffffffu, p2, 4);
            p1 += __shfl_xor_sync(0xffffffffu, p1, 2);
            p2 += __shfl_xor_sync(0xffffffffu, p2, 2);
            p1 += __shfl_xor_sync(0xffffffffu, p1, 1);
            p2 += __shfl_xor_sync(0xffffffffu, p2, 1);
        } else {
            #pragma unroll
            for (int off = 16; off > 0; off >>= 1) {
                p1 += __shfl_xor_sync(0xffffffffu, p1, off);
                p2 += __shfl_xor_sync(0xffffffffu, p2, off);
            }
        }
        float mp = fmaxf(p1, p2);
        if (mp > m) {
            float sc = __expf(m - mp);
            ssum *= sc;
            acc0.x *= sc; acc0.y *= sc; acc0.z *= sc; acc0.w *= sc;
            acc1.x *= sc; acc1.y *= sc; acc1.z *= sc; acc1.w *= sc;
            m = mp;
        }
        float wp = __expf(p1 - m);
        float wq = __expf(p2 - m);
        ssum += wp + wq;
        acc0.x = fmaf(wp, c0.x, fmaf(wq, d0.x, acc0.x));
        acc0.y = fmaf(wp, c0.y, fmaf(wq, d0.y, acc0.y));
        acc0.z = fmaf(wp, c0.z, fmaf(wq, d0.z, acc0.z));
        acc0.w = fmaf(wp, c0.w, fmaf(wq, d0.w, acc0.w));
        acc1.x = fmaf(wp, c1.x, fmaf(wq, d1.x, acc1.x));
        acc1.y = fmaf(wp, c1.y, fmaf(wq, d1.y, acc1.y));
        acc1.z = fmaf(wp, c1.z, fmaf(wq, d1.z, acc1.z));
        acc1.w = fmaf(wp, c1.w, fmaf(wq, d1.w, acc1.w));
    }
    if (s < s1) {   // tail edge
        float4 c0 = A0, c1 = A1;
        float p1;
        p1  =        w0.x * lrelu(c0.x + r0.x);
        p1 = fmaf(w0.y, lrelu(c0.y + r0.y), p1);
        p1 = fmaf(w0.z, lrelu(c0.z + r0.z), p1);
        p1 = fmaf(w0.w, lrelu(c0.w + r0.w), p1);
        p1 = fmaf(w1.x, lrelu(c1.x + r1.x), p1);
        p1 = fmaf(w1.y, lrelu(c1.y + r1.y), p1);
        p1 = fmaf(w1.z, lrelu(c1.z + r1.z), p1);
        p1 = fmaf(w1.w, lrelu(c1.w + r1.w), p1);
        if (LAYER == 1) {
            p1 += __shfl_xor_sync(0xffffffffu, p1, 4);
            p1 += __shfl_xor_sync(0xffffffffu, p1, 2);
            p1 += __shfl_xor_sync(0xffffffffu, p1, 1);
        } else {
            #pragma unroll
            for (int off = 16; off > 0; off >>= 1)
                p1 += __shfl_xor_sync(0xffffffffu, p1, off);
        }
        if (p1 > m) {
            float sc = __expf(m - p1);
            ssum *= sc;
            acc0.x *= sc; acc0.y *= sc; acc0.z *= sc; acc0.w *= sc;
            acc1.x *= sc; acc1.y *= sc; acc1.z *= sc; acc1.w *= sc;
            m = p1;
        }
        float wp = __expf(p1 - m);
        ssum += wp;
        acc0.x = fmaf(wp, c0.x, acc0.x); acc0.y = fmaf(wp, c0.y, acc0.y);
        acc0.z = fmaf(wp, c0.z, acc0.z); acc0.w = fmaf(wp, c0.w, acc0.w);
        acc1.x = fmaf(wp, c1.x, acc1.x); acc1.y = fmaf(wp, c1.y, acc1.y);
        acc1.z = fmaf(wp, c1.z, acc1.z); acc1.w = fmaf(wp, c1.w, acc1.w);
    }

    float inv = 1.0f / (ssum + EPSS);
    const float4* pb = (const float4*)(bias + c);
    float4 b0 = pb[0], b1 = pb[1];
    float v[8] = { acc0.x * inv + b0.x, acc0.y * inv + b0.y,
                   acc0.z * inv + b0.z, acc0.w * inv + b0.w,
                   acc1.x * inv + b1.x, acc1.y * inv + b1.y,
                   acc1.z * inv + b1.z, acc1.w * inv + b1.w };
    if (LAYER == 1) {
        #pragma unroll
        for (int j = 0; j < 8; j++) v[j] = v[j] > 0.0f ? v[j] : expm1f(v[j]);
    }
    float* outp = (LAYER == 1) ? g_h : out_arg;
    float4* po = (float4*)(outp + node * CH + c);
    po[0] = make_float4(v[0], v[1], v[2], v[3]);
    po[1] = make_float4(v[4], v[5], v[6], v[7]);
}

// ================= launcher =================================================
extern "C" void kernel_launch(void* const* d_in, const int* in_sizes, int n_in,
                              void* d_out, int out_size) {
    const float* x     = (const float*)d_in[0];
    const int*   ei    = (const int*)  d_in[1];
    const float* W_l1  = (const float*)d_in[2];
    const float* b_l1  = (const float*)d_in[3];
    const float* W_r1  = (const float*)d_in[4];
    const float* b_r1  = (const float*)d_in[5];
    const float* att1  = (const float*)d_in[6];
    const float* bias1 = (const float*)d_in[7];
    const float* W_l2  = (const float*)d_in[8];
    const float* b_l2  = (const float*)d_in[9];
    const float* W_r2  = (const float*)d_in[10];
    const float* b_r2  = (const float*)d_in[11];
    const float* att2  = (const float*)d_in[12];
    const float* bias2 = (const float*)d_in[13];
    float* out = (float*)d_out;

    const int T = 256;
    int blkN    = (NN + T - 1) / T;
    int blkE    = (ETOT + T - 1) / T;
    int blkNode = (NN + 7) / 8;        // warp per node (R7 layout)
    int blkG1   = (NN + 63) / 64;
    int blkScan = (NN + 1023) / 1024;  // 49
    int blkConvH = (NN * CH + T - 1) / T;
    int blkConvW = (CH * CH + T - 1) / T;

    // CSR build
    zero_deg<<<blkN, T>>>();
    csr_count<<<blkE, T>>>(ei);
    scan1<<<blkScan, 1024>>>();
    scan2<<<1, 64>>>(blkScan);
    scan3<<<blkScan, 1024>>>();
    csr_scatter<<<blkE, T>>>(ei);

    // W conversion (independent of layer-1 data)
    conv_w<<<blkConvW, T>>>(W_l2, W_r2);

    // layer 1
    gemm1_kernel<<<blkG1, T>>>(x, W_l1, b_l1, W_r1, b_r1);
    fused_edge<1><<<blkNode, T>>>(att1, bias1, nullptr);

    // layer 2: bf16 hi/lo staging, HMMA GEMM, fused edge pass
    conv_h<<<blkConvH, T>>>();
    dim3 gmm((NN + 127) / 128, 4);
    gemm_mma<<<gmm, T>>>(b_l2, b_r2);
    fused_edge<2><<<blkNode, T>>>(att2, bias2, out);
}

// round 15
// speedup vs baseline: 1.3429x; 1.3429x over previous
#include <cuda_runtime.h>
#include <cstdint>
#include <math.h>

#define NN    50000
#define EE    400000
#define ETOT  (NN + EE)
#define CH    256
#define KIN   20
#define NEG_SLOPE 0.2f
#define EPSS  1e-16f

// ---------------- scratch (static device globals; no allocations) ----------
__device__ float g_xl1[NN * CH];
__device__ float g_xr1[NN * CH];
__device__ float g_h[NN * CH];
__device__ float g_xl2[NN * CH];
__device__ float g_xr2[NN * CH];
__device__ int   g_deg[NN];
__device__ int   g_off[NN + 1];
__device__ int   g_part[64];
__device__ int   g_csr_src[ETOT];

__device__ __forceinline__ float lrelu(float v) {
    return v > 0.0f ? v : NEG_SLOPE * v;
}

// ---- packed f32x2 (FFMA2) helpers ----
__device__ __forceinline__ unsigned long long pack2(float lo, float hi) {
    unsigned long long r;
    asm("mov.b64 %0, {%1, %2};" : "=l"(r) : "f"(lo), "f"(hi));
    return r;
}
__device__ __forceinline__ unsigned long long fma2(unsigned long long a,
                                                   unsigned long long b,
                                                   unsigned long long c) {
    unsigned long long d;
    asm("fma.rn.f32x2 %0, %1, %2, %3;" : "=l"(d) : "l"(a), "l"(b), "l"(c));
    return d;
}
__device__ __forceinline__ float2 unpack2(unsigned long long v) {
    float lo, hi;
    asm("mov.b64 {%0, %1}, %2;" : "=f"(lo), "=f"(hi) : "l"(v));
    return make_float2(lo, hi);
}

// ================= CSR construction =================
__global__ void zero_deg() {
    int i = blockIdx.x * blockDim.x + threadIdx.x;
    if (i < NN) g_deg[i] = 0;
}

__global__ void csr_count(const int* __restrict__ ei) {
    int e = blockIdx.x * blockDim.x + threadIdx.x;
    if (e >= ETOT) return;
    int dst = (e < EE) ? ei[EE + e] : e - EE;
    atomicAdd(&g_deg[dst], 1);
}

__global__ void scan1() {
    int tid = threadIdx.x;
    int lane = tid & 31, wid = tid >> 5;
    __shared__ int wsum[32];
    int i = blockIdx.x * 1024 + tid;
    int v = (i < NN) ? g_deg[i] : 0;
    if (i < NN) g_deg[i] = 0;
    int x = v;
    #pragma unroll
    for (int o = 1; o < 32; o <<= 1) {
        int y = __shfl_up_sync(0xffffffffu, x, o);
        if (lane >= o) x += y;
    }
    if (lane == 31) wsum[wid] = x;
    __syncthreads();
    if (wid == 0) {
        int w = wsum[lane];
        #pragma unroll
        for (int o = 1; o < 32; o <<= 1) {
            int y = __shfl_up_sync(0xffffffffu, w, o);
            if (lane >= o) w += y;
        }
        wsum[lane] = w;
    }
    __syncthreads();
    int incl = x + (wid > 0 ? wsum[wid - 1] : 0);
    if (i < NN) g_off[i] = incl - v;
    if (tid == 1023) g_part[blockIdx.x] = incl;
}

__global__ void scan2(int nblk) {
    __shared__ int sp[64];
    int t = threadIdx.x;
    sp[t] = (t < nblk) ? g_part[t] : 0;
    __syncthreads();
    if (t == 0) {
        int run = 0;
        for (int i = 0; i < nblk; i++) { int tmp = sp[i]; sp[i] = run; run += tmp; }
    }
    __syncthreads();
    if (t < nblk) g_part[t] = sp[t];
}

__global__ void scan3() {
    int i = blockIdx.x * 1024 + threadIdx.x;
    if (i < NN) g_off[i] += g_part[blockIdx.x];
    if (i == 0) g_off[NN] = ETOT;
}

__global__ void csr_scatter(const int* __restrict__ ei) {
    int e = blockIdx.x * blockDim.x + threadIdx.x;
    if (e >= ETOT) return;
    int src, dst;
    if (e < EE) { src = ei[e]; dst = ei[EE + e]; }
    else        { src = dst = e - EE; }
    int pos = g_off[dst] + atomicAdd(&g_deg[dst], 1);
    g_csr_src[pos] = src;
}

// ================= layer-1 GEMM: x[N,20]@W[20,256]+b, 64 rows/block ========
__global__ void gemm1_kernel(const float* __restrict__ x,
                             const float* __restrict__ Wl, const float* __restrict__ bl,
                             const float* __restrict__ Wr, const float* __restrict__ br) {
    __shared__ float swl[KIN * 256];
    __shared__ float swr[KIN * 256];
    __shared__ float sx[64][KIN];
    int tid = threadIdx.x;
    for (int i = tid; i < KIN * 256; i += 256) { swl[i] = Wl[i]; swr[i] = Wr[i]; }
    int nb = blockIdx.x * 64;
    for (int i = tid; i < 64 * KIN; i += 256) {
        int node = nb + i / KIN;
        sx[i / KIN][i % KIN] = (node < NN) ? x[node * KIN + (i % KIN)] : 0.0f;
    }
    __syncthreads();
    float bL = bl[tid], bR = br[tid];
    #pragma unroll 4
    for (int i = 0; i < 64; i++) {
        int node = nb + i;
        if (node >= NN) break;
        float al = bL, ar = bR;
        #pragma unroll
        for (int k = 0; k < KIN; k++) {
            float xv = sx[i][k];
            al = fmaf(xv, swl[k * 256 + tid], al);
            ar = fmaf(xv, swr[k * 256 + tid], ar);
        }
        g_xl1[node * 256 + tid] = al;
        g_xr1[node * 256 + tid] = ar;
    }
}

// ================= dual layer-2 GEMM, 128x64 tile, 8x4x2 per thread =========
__global__ void __launch_bounds__(256, 2)
gemm_dual(const float* __restrict__ Wl, const float* __restrict__ bl,
          const float* __restrict__ Wr, const float* __restrict__ br) {
    const float* __restrict__ A = g_h;
    __shared__ float As[16][128];
    __shared__ float Bl[16][64];
    __shared__ float Br[16][64];
    int tid = threadIdx.x;
    int tx = tid & 15;
    int ty = tid >> 4;
    int row0 = blockIdx.x * 128;
    int col0 = blockIdx.y * 64;

    unsigned long long accL[8][2], accR[8][2];
    #pragma unroll
    for (int i = 0; i < 8; i++) {
        accL[i][0] = 0ull; accL[i][1] = 0ull;
        accR[i][0] = 0ull; accR[i][1] = 0ull;
    }

    for (int kt = 0; kt < 256; kt += 16) {
        #pragma unroll
        for (int j = 0; j < 8; j++) {
            int i = tid + j * 256;
            int m = i >> 4, k = i & 15;
            int row = row0 + m;
            As[k][m] = (row < NN) ? A[row * 256 + kt + k] : 0.0f;
        }
        #pragma unroll
        for (int j = 0; j < 4; j++) {
            int i = tid + j * 256;
            int k = i >> 6, col = i & 63;
            Bl[k][col] = Wl[(kt + k) * 256 + col0 + col];
            Br[k][col] = Wr[(kt + k) * 256 + col0 + col];
        }
        __syncthreads();
        #pragma unroll
        for (int k = 0; k < 16; k++) {
            float4 a0 = *(const float4*)&As[k][ty * 8];
            float4 a1 = *(const float4*)&As[k][ty * 8 + 4];
            ulonglong2 b  = *(const ulonglong2*)&Bl[k][tx * 4];
            ulonglong2 b2 = *(const ulonglong2*)&Br[k][tx * 4];
            unsigned long long ap[8];
            ap[0] = pack2(a0.x, a0.x); ap[1] = pack2(a0.y, a0.y);
            ap[2] = pack2(a0.z, a0.z); ap[3] = pack2(a0.w, a0.w);
            ap[4] = pack2(a1.x, a1.x); ap[5] = pack2(a1.y, a1.y);
            ap[6] = pack2(a1.z, a1.z); ap[7] = pack2(a1.w, a1.w);
            #pragma unroll
            for (int i = 0; i < 8; i++) {
                accL[i][0] = fma2(ap[i], b.x,  accL[i][0]);
                accL[i][1] = fma2(ap[i], b.y,  accL[i][1]);
                accR[i][0] = fma2(ap[i], b2.x, accR[i][0]);
                accR[i][1] = fma2(ap[i], b2.y, accR[i][1]);
            }
        }
        __syncthreads();
    }
    #pragma unroll
    for (int i = 0; i < 8; i++) {
        int row = row0 + ty * 8 + i;
        if (row >= NN) continue;
        int col = col0 + tx * 4;
        float2 l0 = unpack2(accL[i][0]), l1 = unpack2(accL[i][1]);
        float2 r0 = unpack2(accR[i][0]), r1 = unpack2(accR[i][1]);
        float4 vl, vr;
        vl.x = l0.x + bl[col + 0]; vl.y = l0.y + bl[col + 1];
        vl.z = l1.x + bl[col + 2]; vl.w = l1.y + bl[col + 3];
        vr.x = r0.x + br[col + 0]; vr.y = r0.y + br[col + 1];
        vr.z = r1.x + br[col + 2]; vr.w = r1.y + br[col + 3];
        *(float4*)&g_xl2[row * 256 + col] = vl;
        *(float4*)&g_xr2[row * 256 + col] = vr;
    }
}

// ================= fused edge pass (R7): 2-edge pipelined online softmax ====
template<int LAYER>
__global__ void fused_edge(const float* __restrict__ att,
                           const float* __restrict__ bias,
                           float* __restrict__ out_arg) {
    const float* __restrict__ xl = (LAYER == 1) ? g_xl1 : g_xl2;
    const float* __restrict__ xr = (LAYER == 1) ? g_xr1 : g_xr2;

    int node = (blockIdx.x * blockDim.x + threadIdx.x) >> 5;
    int lane = threadIdx.x & 31;
    if (node >= NN) return;
    int s0 = g_off[node], s1 = g_off[node + 1];
    int c = lane * 8;

    const float4* pr = (const float4*)(xr + node * CH + c);
    float4 r0 = pr[0], r1 = pr[1];
    const float4* pa = (const float4*)(att + c);
    float4 w0 = pa[0], w1 = pa[1];

    float m = -INFINITY, ssum = 0.0f;
    float4 acc0 = make_float4(0.f, 0.f, 0.f, 0.f);
    float4 acc1 = make_float4(0.f, 0.f, 0.f, 0.f);

    float4 A0, A1, B0, B1;
    {
        const float4* p = (const float4*)(xl + g_csr_src[s0] * CH + c);
        A0 = p[0]; A1 = p[1];
    }
    if (s0 + 1 < s1) {
        const float4* p = (const float4*)(xl + g_csr_src[s0 + 1] * CH + c);
        B0 = p[0]; B1 = p[1];
    }

    int s = s0;
    for (; s + 1 < s1; s += 2) {
        float4 c0 = A0, c1 = A1, d0 = B0, d1 = B1;
        if (s + 2 < s1) {
            const float4* p = (const float4*)(xl + g_csr_src[s + 2] * CH + c);
            A0 = p[0]; A1 = p[1];
        }
        if (s + 3 < s1) {
            const float4* p = (const float4*)(xl + g_csr_src[s + 3] * CH + c);
            B0 = p[0]; B1 = p[1];
        }
        float p1, p2;
        p1  =        w0.x * lrelu(c0.x + r0.x);
        p2  =        w0.x * lrelu(d0.x + r0.x);
        p1 = fmaf(w0.y, lrelu(c0.y + r0.y), p1);
        p2 = fmaf(w0.y, lrelu(d0.y + r0.y), p2);
        p1 = fmaf(w0.z, lrelu(c0.z + r0.z), p1);
        p2 = fmaf(w0.z, lrelu(d0.z + r0.z), p2);
        p1 = fmaf(w0.w, lrelu(c0.w + r0.w), p1);
        p2 = fmaf(w0.w, lrelu(d0.w + r0.w), p2);
        p1 = fmaf(w1.x, lrelu(c1.x + r1.x), p1);
        p2 = fmaf(w1.x, lrelu(d1.x + r1.x), p2);
        p1 = fmaf(w1.y, lrelu(c1.y + r1.y), p1);
        p2 = fmaf(w1.y, lrelu(d1.y + r1.y), p2);
        p1 = fmaf(w1.z, lrelu(c1.z + r1.z), p1);
        p2 = fmaf(w1.z, lrelu(d1.z + r1.z), p2);
        p1 = fmaf(w1.w, lrelu(c1.w + r1.w), p1);
        p2 = fmaf(w1.w, lrelu(d1.w + r1.w), p2);
        if (LAYER == 1) {
            p1 += __shfl_xor_sync(0xffffffffu, p1, 4);
            p2 += __shfl_xor_sync(0xffffffffu, p2, 4);
            p1 += __shfl_xor_sync(0xffffffffu, p1, 2);
            p2 += __shfl_xor_sync(0xffffffffu, p2, 2);
            p1 += __shfl_xor_sync(0xffffffffu, p1, 1);
            p2 += __shfl_xor_sync(0xffffffffu, p2, 1);
        } else {
            #pragma unroll
            for (int off = 16; off > 0; off >>= 1) {
                p1 += __shfl_xor_sync(0xffffffffu, p1, off);
                p2 += __shfl_xor_sync(0xffffffffu, p2, off);
            }
        }
        float mp = fmaxf(p1, p2);
        if (mp > m) {
            float sc = __expf(m - mp);
            ssum *= sc;
            acc0.x *= sc; acc0.y *= sc; acc0.z *= sc; acc0.w *= sc;
            acc1.x *= sc; acc1.y *= sc; acc1.z *= sc; acc1.w *= sc;
            m = mp;
        }
        float wp = __expf(p1 - m);
        float wq = __expf(p2 - m);
        ssum += wp + wq;
        acc0.x = fmaf(wp, c0.x, fmaf(wq, d0.x, acc0.x));
        acc0.y = fmaf(wp, c0.y, fmaf(wq, d0.y, acc0.y));
        acc0.z = fmaf(wp, c0.z, fmaf(wq, d0.z, acc0.z));
        acc0.w = fmaf(wp, c0.w, fmaf(wq, d0.w, acc0.w));
        acc1.x = fmaf(wp, c1.x, fmaf(wq, d1.x, acc1.x));
        acc1.y = fmaf(wp, c1.y, fmaf(wq, d1.y, acc1.y));
        acc1.z = fmaf(wp, c1.z, fmaf(wq, d1.z, acc1.z));
        acc1.w = fmaf(wp, c1.w, fmaf(wq, d1.w, acc1.w));
    }
    if (s < s1) {   // tail edge
        float4 c0 = A0, c1 = A1;
        float p1;
        p1  =        w0.x * lrelu(c0.x + r0.x);
        p1 = fmaf(w0.y, lrelu(c0.y + r0.y), p1);
        p1 = fmaf(w0.z, lrelu(c0.z + r0.z), p1);
        p1 = fmaf(w0.w, lrelu(c0.w + r0.w), p1);
        p1 = fmaf(w1.x, lrelu(c1.x + r1.x), p1);
        p1 = fmaf(w1.y, lrelu(c1.y + r1.y), p1);
        p1 = fmaf(w1.z, lrelu(c1.z + r1.z), p1);
        p1 = fmaf(w1.w, lrelu(c1.w + r1.w), p1);
        if (LAYER == 1) {
            p1 += __shfl_xor_sync(0xffffffffu, p1, 4);
            p1 += __shfl_xor_sync(0xffffffffu, p1, 2);
            p1 += __shfl_xor_sync(0xffffffffu, p1, 1);
        } else {
            #pragma unroll
            for (int off = 16; off > 0; off >>= 1)
                p1 += __shfl_xor_sync(0xffffffffu, p1, off);
        }
        if (p1 > m) {
            float sc = __expf(m - p1);
            ssum *= sc;
            acc0.x *= sc; acc0.y *= sc; acc0.z *= sc; acc0.w *= sc;
            acc1.x *= sc; acc1.y *= sc; acc1.z *= sc; acc1.w *= sc;
            m = p1;
        }
        float wp = __expf(p1 - m);
        ssum += wp;
        acc0.x = fmaf(wp, c0.x, acc0.x); acc0.y = fmaf(wp, c0.y, acc0.y);
        acc0.z = fmaf(wp, c0.z, acc0.z); acc0.w = fmaf(wp, c0.w, acc0.w);
        acc1.x = fmaf(wp, c1.x, acc1.x); acc1.y = fmaf(wp, c1.y, acc1.y);
        acc1.z = fmaf(wp, c1.z, acc1.z); acc1.w = fmaf(wp, c1.w, acc1.w);
    }

    float inv = 1.0f / (ssum + EPSS);
    const float4* pb = (const float4*)(bias + c);
    float4 b0 = pb[0], b1 = pb[1];
    float v[8] = { acc0.x * inv + b0.x, acc0.y * inv + b0.y,
                   acc0.z * inv + b0.z, acc0.w * inv + b0.w,
                   acc1.x * inv + b1.x, acc1.y * inv + b1.y,
                   acc1.z * inv + b1.z, acc1.w * inv + b1.w };
    if (LAYER == 1) {
        #pragma unroll
        for (int j = 0; j < 8; j++) v[j] = v[j] > 0.0f ? v[j] : expm1f(v[j]);
    }
    float* outp = (LAYER == 1) ? g_h : out_arg;
    float4* po = (float4*)(outp + node * CH + c);
    po[0] = make_float4(v[0], v[1], v[2], v[3]);
    po[1] = make_float4(v[4], v[5], v[6], v[7]);
}

// ================= launcher =================================================
extern "C" void kernel_launch(void* const* d_in, const int* in_sizes, int n_in,
                              void* d_out, int out_size) {
    const float* x     = (const float*)d_in[0];
    const int*   ei    = (const int*)  d_in[1];
    const float* W_l1  = (const float*)d_in[2];
    const float* b_l1  = (const float*)d_in[3];
    const float* W_r1  = (const float*)d_in[4];
    const float* b_r1  = (const float*)d_in[5];
    const float* att1  = (const float*)d_in[6];
    const float* bias1 = (const float*)d_in[7];
    const float* W_l2  = (const float*)d_in[8];
    const float* b_l2  = (const float*)d_in[9];
    const float* W_r2  = (const float*)d_in[10];
    const float* b_r2  = (const float*)d_in[11];
    const float* att2  = (const float*)d_in[12];
    const float* bias2 = (const float*)d_in[13];
    float* out = (float*)d_out;

    const int T = 256;
    int blkN    = (NN + T - 1) / T;
    int blkE    = (ETOT + T - 1) / T;
    int blkNode = (NN + 7) / 8;        // warp per node (R7 layout)
    int blkG1   = (NN + 63) / 64;
    int blkScan = (NN + 1023) / 1024;  // 49

    // one-time side-stream + events (host resources only; no device memory)
    static cudaStream_t s2 = nullptr;
    static cudaEvent_t evFork = nullptr, evJoin = nullptr;
    if (s2 == nullptr) {
        cudaStreamCreateWithFlags(&s2, cudaStreamNonBlocking);
        cudaEventCreateWithFlags(&evFork, cudaEventDisableTiming);
        cudaEventCreateWithFlags(&evJoin, cudaEventDisableTiming);
    }

    // fork: CSR build on s2, concurrent with gemm1 on the main stream
    cudaEventRecord(evFork, 0);
    cudaStreamWaitEvent(s2, evFork, 0);

    zero_deg<<<blkN, T, 0, s2>>>();
    csr_count<<<blkE, T, 0, s2>>>(ei);
    scan1<<<blkScan, 1024, 0, s2>>>();
    scan2<<<1, 64, 0, s2>>>(blkScan);
    scan3<<<blkScan, 1024, 0, s2>>>();
    csr_scatter<<<blkE, T, 0, s2>>>(ei);
    cudaEventRecord(evJoin, s2);

    // main stream: layer-1 GEMM (independent of CSR)
    gemm1_kernel<<<blkG1, T>>>(x, W_l1, b_l1, W_r1, b_r1);

    // join: fused edge pass needs both CSR and gemm1
    cudaStreamWaitEvent(0, evJoin, 0);
    fused_edge<1><<<blkNode, T>>>(att1, bias1, nullptr);

    // layer 2
    dim3 g2((NN + 127) / 128, 4);
    gemm_dual<<<g2, T>>>(W_l2, b_l2, W_r2, b_r2);
    fused_edge<2><<<blkNode, T>>>(att2, bias2, out);
}